// round 1
// baseline (speedup 1.0000x reference)
#include <cuda_runtime.h>
#include <cuda_bf16.h>

// ZBL basis: per-edge screened Coulomb repulsion with polynomial cutoff,
// scatter-summed into receiver nodes.
//
// Inputs (metadata order):
//   d_in[0]: x               float32 [E, 1]   (E = 3,200,000)
//   d_in[1]: node_attrs      float32 [N, 10]  (N = 100,000)
//   d_in[2]: edge_index      int32   [2, E]
//   d_in[3]: atomic_numbers  int32   [10]
//   d_in[4]: covalent_radii  float32 [119]
// Output: V_ZBL float32 [N]

#define MAX_NODES 100352
#define N_ELEMS   10

// Per-node precomputed record: {Zf, Zf^0.3, covalent_radii[Z], pad}
__device__ float4 g_node[MAX_NODES];

__global__ void node_prep_kernel(const float* __restrict__ attrs,
                                 const int* __restrict__ atomic_numbers,
                                 const float* __restrict__ covalent_radii,
                                 int n_nodes) {
    int i = blockIdx.x * blockDim.x + threadIdx.x;
    if (i >= n_nodes) return;
    const float* a = attrs + (size_t)i * N_ELEMS;
    // argmax (first-max wins, matching jnp.argmax)
    int best = 0;
    float bv = a[0];
#pragma unroll
    for (int j = 1; j < N_ELEMS; j++) {
        float v = a[j];
        if (v > bv) { bv = v; best = j; }
    }
    int Z = atomic_numbers[best];
    float Zf = (float)Z;
    g_node[i] = make_float4(Zf, powf(Zf, 0.3f), covalent_radii[Z], 0.0f);
}

__global__ void zero_out_kernel(float* __restrict__ out, int n) {
    int i = blockIdx.x * blockDim.x + threadIdx.x;
    if (i < n) out[i] = 0.0f;
}

__global__ void edge_kernel(const float* __restrict__ x,
                            const int* __restrict__ edge_index,
                            float* __restrict__ out,
                            int n_edges) {
    int i = blockIdx.x * blockDim.x + threadIdx.x;
    if (i >= n_edges) return;

    int s = edge_index[i];
    int r = edge_index[n_edges + i];
    float xi = x[i];

    float4 nu = g_node[s];
    float4 nv = g_node[r];

    float rmax = nu.z + nv.z;
    // envelope is exactly zero when x >= rmax -> contribution is zero
    if (xi >= rmax) return;

    // a = 0.4543 * 0.529 / (Zu^0.3 + Zv^0.3)
    float inv_a = (nu.y + nv.y) * (1.0f / (0.4543f * 0.529f));
    float t = xi * inv_a;  // r / a

    float phi = 0.1818f  * __expf(-3.2f    * t)
              + 0.5099f  * __expf(-0.9423f * t)
              + 0.2802f  * __expf(-0.4028f * t)
              + 0.02817f * __expf(-0.2016f * t);

    float v = 14.3996f * nu.x * nv.x / xi * phi;

    // polynomial envelope, p = 6:
    // 1 - 28 r^6 + 48 r^7 - 21 r^8  with r = x / rmax
    float rr = xi / rmax;
    float r2 = rr * rr;
    float r3 = r2 * rr;
    float r6 = r3 * r3;
    float env = 1.0f - 28.0f * r6 + 48.0f * r6 * rr - 21.0f * r6 * r2;

    v = 0.5f * v * env;
    atomicAdd(out + r, v);
}

extern "C" void kernel_launch(void* const* d_in, const int* in_sizes, int n_in,
                              void* d_out, int out_size) {
    const float* x              = (const float*)d_in[0];
    const float* node_attrs     = (const float*)d_in[1];
    const int*   edge_index     = (const int*)  d_in[2];
    const int*   atomic_numbers = (const int*)  d_in[3];
    const float* covalent_radii = (const float*)d_in[4];
    float* out = (float*)d_out;

    int n_edges = in_sizes[0];            // E
    int n_nodes = in_sizes[1] / N_ELEMS;  // N

    const int T = 256;
    node_prep_kernel<<<(n_nodes + T - 1) / T, T>>>(node_attrs, atomic_numbers,
                                                   covalent_radii, n_nodes);
    zero_out_kernel<<<(out_size + T - 1) / T, T>>>(out, out_size);
    edge_kernel<<<(n_edges + T - 1) / T, T>>>(x, edge_index, out, n_edges);
}

// round 2
// speedup vs baseline: 1.8765x; 1.8765x over previous
#include <cuda_runtime.h>
#include <cuda_bf16.h>

// ZBL basis: per-edge screened Coulomb repulsion with polynomial cutoff,
// scatter-summed into receiver nodes.
//
// Inputs (metadata order):
//   d_in[0]: x               float32 [E, 1]   (E = 3,200,000)
//   d_in[1]: node_attrs      float32 [N, 10]  (N = 100,000)
//   d_in[2]: edge_index      int32   [2, E]
//   d_in[3]: atomic_numbers  int32   [10]
//   d_in[4]: covalent_radii  float32 [119]
// Output: V_ZBL float32 [N]
//
// Strategy: per-node atomic number Z fits in uint8. Stage the entire Z table
// (100KB) in shared memory per block so the 2 random gathers per edge are
// cheap LDS (bank-conflict-degree cost) instead of fully-divergent LDG
// (32 wavefronts/warp-instr + 32B L2 sector per lane). Z^0.3 and radii come
// from tiny smem LUTs.

#define MAX_NODES 100352   // >= N, multiple of 4 for word copies
#define N_ELEMS   10
#define LUT_SIZE  128      // covers Z in 1..119

__device__ unsigned char g_z[MAX_NODES];

// ---------------------------------------------------------------------------
// Node prep: argmax over 10 attrs -> Z (uint8), zero the output.
// Coalesced: block stages 256 nodes x 10 floats through smem.
// ---------------------------------------------------------------------------
__global__ void node_prep_kernel(const float* __restrict__ attrs,
                                 const int* __restrict__ atomic_numbers,
                                 float* __restrict__ out,
                                 int n_nodes, int out_n) {
    __shared__ float s[256 * N_ELEMS];
    int base = blockIdx.x * 256;
    int nloc = n_nodes - base;
    if (nloc > 256) nloc = 256;
    if (nloc > 0) {
        int total = nloc * N_ELEMS;
        const float* src = attrs + (size_t)base * N_ELEMS;
        for (int k = threadIdx.x; k < total; k += 256) s[k] = src[k];
    }
    __syncthreads();

    int i = base + threadIdx.x;
    if ((int)threadIdx.x < nloc) {
        const float* a = s + threadIdx.x * N_ELEMS;
        int best = 0;
        float bv = a[0];
#pragma unroll
        for (int j = 1; j < N_ELEMS; j++) {
            float v = a[j];
            if (v > bv) { bv = v; best = j; }
        }
        g_z[i] = (unsigned char)atomic_numbers[best];
    }
    if (i < out_n) out[i] = 0.0f;
}

// ---------------------------------------------------------------------------
// Edge kernel: persistent grid-stride, Z table + LUTs in dynamic smem.
// ---------------------------------------------------------------------------
__device__ __forceinline__ void process_edge(
    int s, int r, float xi,
    const unsigned char* __restrict__ s_z,
    const float* __restrict__ s_pow,
    const float* __restrict__ s_rad,
    float* __restrict__ out)
{
    int zu = s_z[s];
    int zv = s_z[r];
    float rmax = s_rad[zu] + s_rad[zv];
    if (xi < rmax) {
        // a = 0.4543 * 0.529 / (Zu^0.3 + Zv^0.3);  t = x / a
        float t = xi * (s_pow[zu] + s_pow[zv]) * (1.0f / (0.4543f * 0.529f));
        float phi = 0.1818f  * __expf(-3.2f    * t)
                  + 0.5099f  * __expf(-0.9423f * t)
                  + 0.2802f  * __expf(-0.4028f * t)
                  + 0.02817f * __expf(-0.2016f * t);
        float v = 14.3996f * (float)zu * (float)zv * __fdividef(phi, xi);

        // polynomial envelope, p=6: 1 - 28 r^6 + 48 r^7 - 21 r^8
        float rr = __fdividef(xi, rmax);
        float r2 = rr * rr;
        float r3 = r2 * rr;
        float r6 = r3 * r3;
        float env = 1.0f - 28.0f * r6 + 48.0f * r6 * rr - 21.0f * r6 * r2;

        atomicAdd(out + r, 0.5f * v * env);
    }
}

__global__ void edge_kernel(const float* __restrict__ x,
                            const int* __restrict__ ei,
                            const float* __restrict__ radii_g,
                            float* __restrict__ out,
                            int n_edges, int n_nodes) {
    extern __shared__ char smem[];
    float* s_pow = (float*)smem;                       // LUT_SIZE floats
    float* s_rad = s_pow + LUT_SIZE;                   // LUT_SIZE floats
    unsigned char* s_z = (unsigned char*)(s_rad + LUT_SIZE);

    int tid = threadIdx.x;
    int nt = blockDim.x;

    // LUTs: Z^0.3 and covalent radii, indexed directly by Z
    for (int z = tid; z < LUT_SIZE; z += nt) {
        s_pow[z] = powf((float)z, 0.3f);
        s_rad[z] = (z < 119) ? radii_g[z] : 0.0f;
    }
    // Copy Z table into smem (word-wide, coalesced; table is L2-resident)
    {
        const unsigned int* gz32 = (const unsigned int*)g_z;
        unsigned int* sz32 = (unsigned int*)s_z;
        int nwords = (n_nodes + 3) >> 2;
        for (int w = tid; w < nwords; w += nt) sz32[w] = gz32[w];
    }
    __syncthreads();

    const int4*   si = (const int4*)ei;
    const int4*   ri = (const int4*)(ei + n_edges);
    const float4* x4 = (const float4*)x;
    int n4 = n_edges >> 2;
    int gstride = gridDim.x * nt;

    for (int g = blockIdx.x * nt + tid; g < n4; g += gstride) {
        int4 ss = si[g];
        int4 rr = ri[g];
        float4 xx = x4[g];
        process_edge(ss.x, rr.x, xx.x, s_z, s_pow, s_rad, out);
        process_edge(ss.y, rr.y, xx.y, s_z, s_pow, s_rad, out);
        process_edge(ss.z, rr.z, xx.z, s_z, s_pow, s_rad, out);
        process_edge(ss.w, rr.w, xx.w, s_z, s_pow, s_rad, out);
    }
    // scalar tail
    for (int i = (n4 << 2) + blockIdx.x * nt + tid; i < n_edges; i += gstride) {
        process_edge(ei[i], ei[n_edges + i], x[i], s_z, s_pow, s_rad, out);
    }
}

extern "C" void kernel_launch(void* const* d_in, const int* in_sizes, int n_in,
                              void* d_out, int out_size) {
    const float* x              = (const float*)d_in[0];
    const float* node_attrs     = (const float*)d_in[1];
    const int*   edge_index     = (const int*)  d_in[2];
    const int*   atomic_numbers = (const int*)  d_in[3];
    const float* covalent_radii = (const float*)d_in[4];
    float* out = (float*)d_out;

    int n_edges = in_sizes[0];            // E
    int n_nodes = in_sizes[1] / N_ELEMS;  // N

    // node prep + output zeroing
    {
        int cover = n_nodes > out_size ? n_nodes : out_size;
        int blocks = (cover + 255) / 256;
        node_prep_kernel<<<blocks, 256>>>(node_attrs, atomic_numbers, out,
                                          n_nodes, out_size);
    }

    // edge kernel: dynamic smem = 2 LUTs + Z table
    int smem_bytes = 2 * LUT_SIZE * (int)sizeof(float) + MAX_NODES;
    cudaFuncSetAttribute(edge_kernel,
                         cudaFuncAttributeMaxDynamicSharedMemorySize,
                         smem_bytes);
    // 2 blocks per SM (smem-limited), persistent grid-stride
    edge_kernel<<<304, 1024, smem_bytes>>>(x, edge_index, covalent_radii, out,
                                           n_edges, n_nodes);
}